// round 3
// baseline (speedup 1.0000x reference)
#include <cuda_runtime.h>
#include <cuda_bf16.h>

#define NN 50000
#define EE 800000
#define GG 512
#define CC 128

// ---------------- scratch (static device arrays; no allocation) ----------------
__device__ float g_h0[NN*CC];
__device__ float g_h1[NN*CC];
__device__ float g_t1[NN*CC];
__device__ float g_t2[NN*CC];
__device__ float g_deg[NN];
__device__ float g_dis[NN];
__device__ float g_norm[EE];
__device__ float g_pool[GG*CC];
__device__ float g_cnt[GG];
__device__ float g_chsum[CC];
__device__ float g_chsq[CC];
__device__ float g_bna[CC];
__device__ float g_bnb[CC];

// ---------------- small utility kernels ----------------
__global__ void k_zero4(float* __restrict__ p, int n4) {
    int i = blockIdx.x * blockDim.x + threadIdx.x;
    if (i < n4) ((float4*)p)[i] = make_float4(0.f, 0.f, 0.f, 0.f);
}

__global__ void k_deg(const int* __restrict__ row) {
    int e = blockIdx.x * blockDim.x + threadIdx.x;
    if (e < EE) atomicAdd(&g_deg[row[e]], 1.0f);
}

__global__ void k_dis() {
    int n = blockIdx.x * blockDim.x + threadIdx.x;
    if (n < NN) {
        float d = g_deg[n];
        g_dis[n] = (d > 0.f) ? rsqrtf(fmaxf(d, 1.0f)) : 0.f;
    }
}

__global__ void k_norm(const int* __restrict__ row, const int* __restrict__ col) {
    int e = blockIdx.x * blockDim.x + threadIdx.x;
    if (e < EE) g_norm[e] = -(g_dis[row[e]] * g_dis[col[e]]);
}

// AtomEncoder: h0[n,c] = sum_f atom_emb[f, x[n,f], c]
__global__ void k_embed(const float* __restrict__ emb, const int* __restrict__ x) {
    int n = blockIdx.x;
    __shared__ int xs[9];
    if (threadIdx.x < 9) xs[threadIdx.x] = x[n * 9 + threadIdx.x];
    __syncthreads();
    int c = threadIdx.x;
    float s = 0.f;
#pragma unroll
    for (int f = 0; f < 9; f++)
        s += emb[((f * 119) + xs[f]) * CC + c];
    g_h0[n * CC + c] = s;
}

// Lhat: dst[row[e]] += norm[e] * src[col[e]]   (one warp per edge, vec4 reduction)
__global__ void k_lhat(const float* __restrict__ src, float* __restrict__ dst,
                       const int* __restrict__ row, const int* __restrict__ col) {
    int gt = blockIdx.x * blockDim.x + threadIdx.x;
    int e = gt >> 5;
    if (e >= EE) return;
    int lane = threadIdx.x & 31;
    int r = row[e];
    int c = col[e];
    float w = g_norm[e];
    float4 v = ((const float4*)(src + (size_t)c * CC))[lane];
    float* d = dst + (size_t)r * CC + lane * 4;
    asm volatile("red.global.add.v4.f32 [%0], {%1,%2,%3,%4};"
                 :: "l"(d), "f"(v.x * w), "f"(v.y * w), "f"(v.z * w), "f"(v.w * w)
                 : "memory");
}

// t2 = 2*t2 - h  (Chebyshev recurrence fix-up), float4
__global__ void k_tx2fix(const float* __restrict__ h, float* __restrict__ t2, int n4) {
    int i = blockIdx.x * blockDim.x + threadIdx.x;
    if (i < n4) {
        float4 t = ((float4*)t2)[i];
        float4 hh = ((const float4*)h)[i];
        t.x = 2.f * t.x - hh.x;
        t.y = 2.f * t.y - hh.y;
        t.z = 2.f * t.z - hh.z;
        t.w = 2.f * t.w - hh.w;
        ((float4*)t2)[i] = t;
    }
}

// out = relu([A0|A1|A2] @ W + b),  A* are [N,128], W is [384,128] (= (3,128,128) contiguous)
// BM=64, BN=128, BK=16, 256 threads, 8x4 microtile per thread.
__global__ void __launch_bounds__(256)
k_cheb_mm(const float* __restrict__ A0, const float* __restrict__ A1,
          const float* __restrict__ A2, const float* __restrict__ W,
          const float* __restrict__ bias, float* __restrict__ out) {
    __shared__ float As[16][65];
    __shared__ __align__(16) float Bs[16][128];
    int tid = threadIdx.x;
    int tx = tid & 31;   // col group: cols tx*4 .. tx*4+3
    int ty = tid >> 5;   // row group: rows ty*8 .. ty*8+7
    int m0 = blockIdx.x * 64;

    float acc[8][4];
#pragma unroll
    for (int r = 0; r < 8; r++)
#pragma unroll
        for (int j = 0; j < 4; j++) acc[r][j] = 0.f;

    const float* srcs[3] = {A0, A1, A2};

    for (int kc = 0; kc < 384; kc += 16) {
        const float* S = srcs[kc >> 7];
        int ksub0 = kc & 127;
        // A tile: 64 rows x 16 k
#pragma unroll
        for (int i = 0; i < 4; i++) {
            int eid = i * 256 + tid;
            int m = eid >> 4;
            int kk = eid & 15;
            int rowg = m0 + m;
            As[kk][m] = (rowg < NN) ? S[(size_t)rowg * CC + ksub0 + kk] : 0.f;
        }
        // B tile: 16 k x 128 cols (row-major, float4 coalesced)
#pragma unroll
        for (int i = 0; i < 2; i++) {
            int fid = i * 256 + tid;
            int kk = fid >> 5;
            int c4 = fid & 31;
            ((float4*)&Bs[kk][0])[c4] = ((const float4*)(W + (size_t)(kc + kk) * CC))[c4];
        }
        __syncthreads();
#pragma unroll
        for (int kk = 0; kk < 16; kk++) {
            float4 b = ((float4*)&Bs[kk][0])[tx];
#pragma unroll
            for (int r = 0; r < 8; r++) {
                float a = As[kk][ty * 8 + r];
                acc[r][0] += a * b.x;
                acc[r][1] += a * b.y;
                acc[r][2] += a * b.z;
                acc[r][3] += a * b.w;
            }
        }
        __syncthreads();
    }

    float4 bb = ((const float4*)bias)[tx];
#pragma unroll
    for (int r = 0; r < 8; r++) {
        int rowg = m0 + ty * 8 + r;
        if (rowg < NN) {
            float4 o;
            o.x = fmaxf(acc[r][0] + bb.x, 0.f);
            o.y = fmaxf(acc[r][1] + bb.y, 0.f);
            o.z = fmaxf(acc[r][2] + bb.z, 0.f);
            o.w = fmaxf(acc[r][3] + bb.w, 0.f);
            ((float4*)(out + (size_t)rowg * CC))[tx] = o;
        }
    }
}

// per-graph node counts
__global__ void k_cnt(const int* __restrict__ batch) {
    int n = blockIdx.x * blockDim.x + threadIdx.x;
    if (n < NN) atomicAdd(&g_cnt[batch[n]], 1.0f);
}

// channel sums/sumsq (for BN) + per-graph pooling sums (batch is sorted -> run accumulation)
__global__ void k_statspool(const float* __restrict__ h, const int* __restrict__ batch) {
    int c = threadIdx.x;          // 128 threads = channels
    int base = blockIdx.x * 128;  // 128 nodes per block
    float s = 0.f, sq = 0.f, acc = 0.f;
    int cur = -1;
    for (int r = 0; r < 128; r++) {
        int n = base + r;
        if (n >= NN) break;
        int g = batch[n];  // broadcast load
        float v = h[(size_t)n * CC + c];
        s += v;
        sq += v * v;
        if (g != cur) {
            if (cur >= 0) atomicAdd(&g_pool[cur * CC + c], acc);
            cur = g;
            acc = 0.f;
        }
        acc += v;
    }
    if (cur >= 0) atomicAdd(&g_pool[cur * CC + c], acc);
    atomicAdd(&g_chsum[c], s);
    atomicAdd(&g_chsq[c], sq);
}

// BN folded into post-pool affine: a = gamma*invstd, b = beta - mu*a
__global__ void k_bnprep(const float* __restrict__ gamma, const float* __restrict__ beta) {
    int c = threadIdx.x;
    float mu = g_chsum[c] * (1.0f / NN);
    float var = fmaxf(g_chsq[c] * (1.0f / NN) - mu * mu, 0.f);
    float inv = rsqrtf(var + 1e-5f);
    float a = gamma[c] * inv;
    g_bna[c] = a;
    g_bnb[c] = beta[c] - mu * a;
}

// final MLP: one thread per graph
__global__ void k_mlp(const float* __restrict__ lw1, const float* __restrict__ lb1,
                      const float* __restrict__ lw2, const float* __restrict__ lb2,
                      float* __restrict__ out) {
    int g = blockIdx.x * blockDim.x + threadIdx.x;
    if (g >= GG) return;
    float inv = 1.0f / fmaxf(g_cnt[g], 1.0f);
    float hid[16];
#pragma unroll
    for (int j = 0; j < 16; j++) hid[j] = lb1[j];
#pragma unroll 4
    for (int c = 0; c < CC; c++) {
        float pb = g_pool[g * CC + c] * inv * g_bna[c] + g_bnb[c];
        const float4* w4 = (const float4*)(lw1 + c * 16);
#pragma unroll
        for (int q = 0; q < 4; q++) {
            float4 w = w4[q];
            hid[q * 4 + 0] += pb * w.x;
            hid[q * 4 + 1] += pb * w.y;
            hid[q * 4 + 2] += pb * w.z;
            hid[q * 4 + 3] += pb * w.w;
        }
    }
    float o0 = lb2[0], o1 = lb2[1];
#pragma unroll
    for (int j = 0; j < 16; j++) {
        float r = fmaxf(hid[j], 0.f);
        o0 += r * lw2[j * 2 + 0];
        o1 += r * lw2[j * 2 + 1];
    }
    out[g * 2 + 0] = o0;
    out[g * 2 + 1] = o1;
}

// ---------------- launcher ----------------
extern "C" void kernel_launch(void* const* d_in, const int* in_sizes, int n_in,
                              void* d_out, int out_size) {
    const float* atom_emb = (const float*)d_in[0];
    const float* W1   = (const float*)d_in[1];
    const float* b1   = (const float*)d_in[2];
    const float* W3   = (const float*)d_in[3];
    const float* b3   = (const float*)d_in[4];
    const float* gam  = (const float*)d_in[5];
    const float* bet  = (const float*)d_in[6];
    const float* lw1  = (const float*)d_in[7];
    const float* lb1  = (const float*)d_in[8];
    const float* lw2  = (const float*)d_in[9];
    const float* lb2  = (const float*)d_in[10];
    const int*   x    = (const int*)d_in[11];
    const int*   ei   = (const int*)d_in[12];
    const int*   batch= (const int*)d_in[13];
    const int* row = ei;
    const int* col = ei + EE;
    float* out = (float*)d_out;

    float *h0, *h1, *t1, *t2, *deg, *pool, *cnt, *chsum, *chsq;
    cudaGetSymbolAddress((void**)&h0, g_h0);
    cudaGetSymbolAddress((void**)&h1, g_h1);
    cudaGetSymbolAddress((void**)&t1, g_t1);
    cudaGetSymbolAddress((void**)&t2, g_t2);
    cudaGetSymbolAddress((void**)&deg, g_deg);
    cudaGetSymbolAddress((void**)&pool, g_pool);
    cudaGetSymbolAddress((void**)&cnt, g_cnt);
    cudaGetSymbolAddress((void**)&chsum, g_chsum);
    cudaGetSymbolAddress((void**)&chsq, g_chsq);

    const int z4 = NN * CC / 4;                 // 1.6M float4s
    const int ZB = (z4 + 255) / 256;
    const int EB = (EE + 255) / 256;
    const int NB = (NN + 255) / 256;
    const int LHAT_B = (EE * 32 + 255) / 256;   // one warp per edge
    const int MM_B = (NN + 63) / 64;

    // degrees / normalization
    k_zero4<<<(NN / 4 + 255) / 256, 256>>>(deg, NN / 4);
    k_deg<<<EB, 256>>>(row);
    k_dis<<<NB, 256>>>();
    k_norm<<<EB, 256>>>(row, col);

    // atom embedding
    k_embed<<<NN, 128>>>(atom_emb, x);

    // conv1
    k_zero4<<<ZB, 256>>>(t1, z4);
    k_lhat<<<LHAT_B, 256>>>(h0, t1, row, col);
    k_zero4<<<ZB, 256>>>(t2, z4);
    k_lhat<<<LHAT_B, 256>>>(t1, t2, row, col);
    k_tx2fix<<<ZB, 256>>>(h0, t2, z4);
    k_cheb_mm<<<MM_B, 256>>>(h0, t1, t2, W1, b1, h1);

    // conv2 (conv3 weights), writes h2 into h0
    k_zero4<<<ZB, 256>>>(t1, z4);
    k_lhat<<<LHAT_B, 256>>>(h1, t1, row, col);
    k_zero4<<<ZB, 256>>>(t2, z4);
    k_lhat<<<LHAT_B, 256>>>(t1, t2, row, col);
    k_tx2fix<<<ZB, 256>>>(h1, t2, z4);
    k_cheb_mm<<<MM_B, 256>>>(h1, t1, t2, W3, b3, h0);

    // BN stats + pooling (BN affine applied post-pool; it commutes with mean)
    k_zero4<<<(GG * CC / 4 + 255) / 256, 256>>>(pool, GG * CC / 4);
    k_zero4<<<1, 128>>>(cnt, GG / 4);
    k_zero4<<<1, 32>>>(chsum, CC / 4);
    k_zero4<<<1, 32>>>(chsq, CC / 4);
    k_cnt<<<NB, 256>>>(batch);
    k_statspool<<<(NN + 127) / 128, 128>>>(h0, batch);
    k_bnprep<<<1, 128>>>(gam, bet);

    // head MLP
    k_mlp<<<2, 256>>>(lw1, lb1, lw2, lb2, out);
}